// round 2
// baseline (speedup 1.0000x reference)
#include <cuda_runtime.h>
#include <cstdint>
#include <cmath>

#define NN   16000
#define EE   512000
#define FF   200
#define HH   256
#define NK0  10
#define NK1  5
#define NOUTC 16

// ---------------- device scratch (no allocations allowed) ----------------
__device__ float g_t0[NN*HH];
__device__ float g_h1[NN*HH];
__device__ float g_h2[NN*HH];
__device__ float g_bottom[NN*HH];
__device__ int   g_srcs[EE];
__device__ float g_wn[EE];
__device__ int   g_rowptr[NN+1];
__device__ int   g_cnt[NN];
__device__ int   g_fill[NN];
__device__ float g_degw[NN];
__device__ float g_dinv[NN];
__device__ float g_selfn[NN];
__device__ int   g_a0[NN];
__device__ float g_xc0[NK0*HH];
__device__ float g_adj0[NK0*NK0];
__device__ float g_lat1[NK0*HH];
__device__ int   g_a1[NK0];
__device__ float g_lat2[NK1*HH];
__device__ float g_contrib[NK0*HH];

// ---------------- threefry2x32 (exact JAX semantics) ----------------
__host__ __device__ inline void tf2x32(uint32_t k0, uint32_t k1, uint32_t x0, uint32_t x1,
                                       uint32_t& o0, uint32_t& o1) {
  uint32_t ks2 = k0 ^ k1 ^ 0x1BD11BDAu;
#define ROTL32(x,d) (((x)<<(d))|((x)>>(32-(d))))
#define TFRND(r) { x0 += x1; x1 = ROTL32(x1,(r)); x1 ^= x0; }
  x0 += k0; x1 += k1;
  TFRND(13) TFRND(15) TFRND(26) TFRND(6)   x0 += k1;  x1 += ks2 + 1u;
  TFRND(17) TFRND(29) TFRND(16) TFRND(24)  x0 += ks2; x1 += k0 + 2u;
  TFRND(13) TFRND(15) TFRND(26) TFRND(6)   x0 += k0;  x1 += k1 + 3u;
  TFRND(17) TFRND(29) TFRND(16) TFRND(24)  x0 += k1;  x1 += ks2 + 4u;
  TFRND(13) TFRND(15) TFRND(26) TFRND(6)   x0 += ks2; x1 += k0 + 5u;
  o0 = x0; o1 = x1;
#undef TFRND
#undef ROTL32
}

__device__ __forceinline__ float gumbel_at(uint32_t k0, uint32_t k1, uint32_t t, uint32_t half) {
  uint32_t a, b, bits;
  if (t < half) { tf2x32(k0, k1, t, t + half, a, b); bits = a; }
  else          { tf2x32(k0, k1, t - half, t, a, b); bits = b; }
  float u01 = __uint_as_float((bits >> 9) | 0x3f800000u) - 1.0f;
  float u = fmaxf(1e-10f, u01 * (1.0f - 1e-10f) + 1e-10f);
  return -logf(-logf(u));
}

// ---------------- helpers ----------------
__device__ __forceinline__ float blockReduceSum256(float v, float* red) {
#pragma unroll
  for (int o = 16; o; o >>= 1) v += __shfl_xor_sync(0xffffffffu, v, o);
  int w = threadIdx.x >> 5;
  if ((threadIdx.x & 31) == 0) red[w] = v;
  __syncthreads();
  float r;
  if (threadIdx.x < 8) {
    r = red[threadIdx.x];
#pragma unroll
    for (int o = 4; o; o >>= 1) r += __shfl_xor_sync(0xffu, r, o);
    if (threadIdx.x == 0) red[0] = r;
  }
  __syncthreads();
  r = red[0];
  __syncthreads();
  return r;
}

// ---------------- graph preprocessing ----------------
__global__ void k_prep() {
  int i = blockIdx.x * blockDim.x + threadIdx.x;
  if (i < NN) { g_cnt[i] = 0; g_fill[i] = 0; g_degw[i] = 0.f; }
  if (i < NK0*HH) g_xc0[i] = 0.f;
  if (i < NK0*NK0) g_adj0[i] = 0.f;
}

__global__ void k_hist(const int* __restrict__ ei, const float* __restrict__ ew) {
  int e = blockIdx.x * blockDim.x + threadIdx.x;
  if (e >= EE) return;
  int d = ei[EE + e];
  atomicAdd(&g_cnt[d], 1);
  atomicAdd(&g_degw[d], ew[e]);
}

__global__ void k_scan() {
  __shared__ int totals[256];
  const int CH = 63;
  int t = threadIdx.x;
  int s0 = t * CH;
  int s1 = s0 + CH; if (s1 > NN) s1 = NN;
  int s = 0;
  for (int i = s0; i < s1; i++) s += g_cnt[i];
  totals[t] = s;
  __syncthreads();
  if (t == 0) {
    int run = 0;
    for (int i = 0; i < 256; i++) { int tmp = totals[i]; totals[i] = run; run += tmp; }
  }
  __syncthreads();
  int run = totals[t];
  for (int i = s0; i < s1; i++) { g_rowptr[i] = run; run += g_cnt[i]; }
  if (s0 < NN && s1 == NN) g_rowptr[NN] = run;
}

__global__ void k_dinv() {
  int i = blockIdx.x * blockDim.x + threadIdx.x;
  if (i >= NN) return;
  float deg = g_degw[i] + 1.0f;
  float di = rsqrtf(deg);
  g_dinv[i] = di;
  g_selfn[i] = di * di;
}

__global__ void k_scatter(const int* __restrict__ ei, const float* __restrict__ ew) {
  int e = blockIdx.x * blockDim.x + threadIdx.x;
  if (e >= EE) return;
  int s = ei[e], d = ei[EE + e];
  int pos = g_rowptr[d] + atomicAdd(&g_fill[d], 1);
  g_srcs[pos] = s;
  g_wn[pos] = ew[e] * g_dinv[s] * g_dinv[d];
}

// ---------------- SGEMM (N tile 128), fused epilogues ----------------
// epi: 0 none, 1 +bias, 2 +bias+relu, 3 +bias+contrib[a0[row]]+relu
__global__ void __launch_bounds__(256) k_sgemm(
    const float* __restrict__ A, const float* __restrict__ B, float* __restrict__ C,
    int K, int lda, int ldb, int ldc, int accumulate, int epi,
    const float* __restrict__ bias)
{
  const int BM = 128, BK = 8;
  __shared__ float As[BK][BM + 4];
  __shared__ float Bs[BK][128];
  int tid = threadIdx.x;
  int bm = blockIdx.y * BM, bn = blockIdx.x * 128;
  int tx = tid & 15, ty = tid >> 4;
  float cr[8][8];
#pragma unroll
  for (int i = 0; i < 8; i++)
#pragma unroll
    for (int j = 0; j < 8; j++) cr[i][j] = 0.f;
  int arow = tid >> 1, acol = (tid & 1) * 4;
  int brow = tid >> 5, bcol = (tid & 31) * 4;
  const float* Ap = A + (size_t)(bm + arow) * lda + acol;
  const float* Bp = B + (size_t)brow * ldb + bn + bcol;
  for (int k0 = 0; k0 < K; k0 += BK) {
    float4 av = *reinterpret_cast<const float4*>(Ap + k0);
    float4 bv = *reinterpret_cast<const float4*>(Bp + (size_t)k0 * ldb);
    As[acol + 0][arow] = av.x; As[acol + 1][arow] = av.y;
    As[acol + 2][arow] = av.z; As[acol + 3][arow] = av.w;
    *reinterpret_cast<float4*>(&Bs[brow][bcol]) = bv;
    __syncthreads();
#pragma unroll
    for (int k = 0; k < BK; k++) {
      float4 a0 = *reinterpret_cast<const float4*>(&As[k][ty * 8]);
      float4 a1 = *reinterpret_cast<const float4*>(&As[k][ty * 8 + 4]);
      float4 b0 = *reinterpret_cast<const float4*>(&Bs[k][tx * 8]);
      float4 b1 = *reinterpret_cast<const float4*>(&Bs[k][tx * 8 + 4]);
      float a[8] = {a0.x, a0.y, a0.z, a0.w, a1.x, a1.y, a1.z, a1.w};
      float b[8] = {b0.x, b0.y, b0.z, b0.w, b1.x, b1.y, b1.z, b1.w};
#pragma unroll
      for (int i = 0; i < 8; i++)
#pragma unroll
        for (int j = 0; j < 8; j++) cr[i][j] = fmaf(a[i], b[j], cr[i][j]);
    }
    __syncthreads();
  }
#pragma unroll
  for (int i = 0; i < 8; i++) {
    int r = bm + ty * 8 + i;
    const float* rt = (epi == 3) ? (g_contrib + (size_t)g_a0[r] * HH) : nullptr;
    float* Cr = C + (size_t)r * ldc + bn + tx * 8;
#pragma unroll
    for (int j = 0; j < 8; j++) {
      int c = bn + tx * 8 + j;
      float v = cr[i][j];
      if (accumulate) v += Cr[j];
      if (epi >= 1) v += bias[c];
      if (epi == 3) v += rt[c];
      if (epi >= 2) v = fmaxf(v, 0.f);
      Cr[j] = v;
    }
  }
}

// ---------------- SpMM + self loop + bias + LayerNorm + ReLU ----------------
__global__ void __launch_bounds__(256) k_spmm_ln_relu(
    const float* __restrict__ hin, float* __restrict__ out,
    const float* __restrict__ bias, const float* __restrict__ lng,
    const float* __restrict__ lnb)
{
  int v = blockIdx.x, f = threadIdx.x;
  int p0 = g_rowptr[v], p1 = g_rowptr[v + 1];
  float acc = hin[(size_t)v * HH + f] * g_selfn[v];
  int p = p0;
  for (; p + 4 <= p1; p += 4) {
    int s0 = g_srcs[p], s1 = g_srcs[p + 1], s2 = g_srcs[p + 2], s3 = g_srcs[p + 3];
    float w0 = g_wn[p], w1 = g_wn[p + 1], w2 = g_wn[p + 2], w3 = g_wn[p + 3];
    acc = fmaf(hin[(size_t)s0 * HH + f], w0, acc);
    acc = fmaf(hin[(size_t)s1 * HH + f], w1, acc);
    acc = fmaf(hin[(size_t)s2 * HH + f], w2, acc);
    acc = fmaf(hin[(size_t)s3 * HH + f], w3, acc);
  }
  for (; p < p1; ++p) acc = fmaf(hin[(size_t)g_srcs[p] * HH + f], g_wn[p], acc);
  acc += bias[f];
  __shared__ float red[8];
  float mean = blockReduceSum256(acc, red) * (1.0f / HH);
  float d = acc - mean;
  float var = blockReduceSum256(d * d, red) * (1.0f / HH);
  out[(size_t)v * HH + f] = fmaxf(0.f, d * rsqrtf(var + 1e-5f) * lng[f] + lnb[f]);
}

// ---------------- level-0 assignment ----------------
__global__ void __launch_bounds__(256) k_assign0(
    const float* __restrict__ bottom, const float* __restrict__ W,
    const float* __restrict__ bias, uint32_t kk0, uint32_t kk1)
{
  int warp = threadIdx.x >> 5, lane = threadIdx.x & 31;
  int v = blockIdx.x * 8 + warp;
  float acc[NK0];
#pragma unroll
  for (int c = 0; c < NK0; c++) acc[c] = 0.f;
  const float* br = bottom + (size_t)v * HH;
  for (int k = lane; k < HH; k += 32) {
    float bv = br[k];
#pragma unroll
    for (int c = 0; c < NK0; c++) acc[c] = fmaf(bv, W[k * NK0 + c], acc[c]);
  }
#pragma unroll
  for (int c = 0; c < NK0; c++) {
#pragma unroll
    for (int o = 16; o; o >>= 1) acc[c] += __shfl_xor_sync(0xffffffffu, acc[c], o);
  }
  if (lane == 0) {
    int best = 0; float bz = -1e30f;
#pragma unroll
    for (int c = 0; c < NK0; c++) {
      float z = acc[c] + bias[c] + gumbel_at(kk0, kk1, (uint32_t)(v * NK0 + c), (uint32_t)(NN * NK0 / 2));
      if (z > bz) { bz = z; best = c; }
    }
    g_a0[v] = best;
  }
}

// ---------------- cluster feature sums ----------------
__global__ void __launch_bounds__(256) k_xc0() {
  __shared__ float acc[NK0 * HH];
  int t = threadIdx.x;
#pragma unroll
  for (int r = 0; r < NK0; r++) acc[r * HH + t] = 0.f;
  __syncthreads();
  int v0 = blockIdx.x * 64;
  for (int n = 0; n < 64; n++) {
    int v = v0 + n;
    int c = g_a0[v];
    acc[c * HH + t] += g_bottom[(size_t)v * HH + t];
  }
  __syncthreads();
  for (int r = 0; r < NK0; r++) atomicAdd(&g_xc0[r * HH + t], acc[r * HH + t]);
}

// ---------------- coarse adjacency histogram ----------------
__global__ void __launch_bounds__(256) k_adj0(const int* __restrict__ ei) {
  __shared__ float a[NK0 * NK0];
  int t = threadIdx.x;
  if (t < NK0 * NK0) a[t] = 0.f;
  __syncthreads();
  int base = blockIdx.x * 4096;
  for (int i = t; i < 4096; i += 256) {
    int e = base + i;
    int cs = g_a0[ei[e]], cd = g_a0[ei[EE + e]];
    atomicAdd(&a[cs * NK0 + cd], 1.0f);
  }
  __syncthreads();
  if (t < NK0 * NK0) atomicAdd(&g_adj0[t], a[t]);
}

// ---------------- level-0 coarsening ----------------
__global__ void __launch_bounds__(256) k_level0(const float* __restrict__ encW,
                                                const float* __restrict__ encb) {
  int f = threadIdx.x;
  __shared__ float xcn[NK0][HH];
  __shared__ float adjn[NK0 * NK0];
  __shared__ float msh[NK0][HH];
  __shared__ float red[8];
  for (int r = 0; r < NK0; r++) {
    float x = g_xc0[r * HH + f];
    float ss = blockReduceSum256(x * x, red);
    float nrm = fmaxf(sqrtf(ss), 1e-12f);
    xcn[r][f] = x / nrm;
  }
  float av = (f < NK0 * NK0) ? g_adj0[f] : 0.f;
  float s = blockReduceSum256(av, red);
  if (f < NK0 * NK0) { adjn[f] = av / s; g_adj0[f] = av / s; }
  __syncthreads();
  for (int r = 0; r < NK0; r++) {
    float m = 0.f;
#pragma unroll
    for (int c = 0; c < NK0; c++) m = fmaf(adjn[r * NK0 + c], xcn[c][f], m);
    msh[r][f] = m;
  }
  __syncthreads();
  float acc[NK0];
#pragma unroll
  for (int r = 0; r < NK0; r++) acc[r] = 0.f;
  for (int k = 0; k < HH; k++) {
    float w = encW[(size_t)k * HH + f];
#pragma unroll
    for (int r = 0; r < NK0; r++) acc[r] = fmaf(msh[r][k], w, acc[r]);
  }
  float bb = encb[f];
#pragma unroll
  for (int r = 0; r < NK0; r++) g_lat1[r * HH + f] = tanhf(acc[r] + bb);
}

// ---------------- level-1 ----------------
__global__ void __launch_bounds__(256) k_level1(
    const float* __restrict__ linW, const float* __restrict__ linb,
    const float* __restrict__ encW, const float* __restrict__ encb,
    uint32_t kk0, uint32_t kk1)
{
  int f = threadIdx.x;
  __shared__ float lg[NK0 * NK1];
  __shared__ int a1s[NK0];
  __shared__ float xcn[NK1][HH];
  __shared__ float adj1[NK1 * NK1];
  __shared__ float m1[NK1][HH];
  __shared__ float red[8];
  if (f < NK0 * NK1) {
    int r = f / NK1, c = f % NK1;
    float acc = linb[c];
    for (int k = 0; k < HH; k++) acc = fmaf(g_lat1[r * HH + k], linW[k * NK1 + c], acc);
    lg[f] = acc;
  }
  if (f < NK1 * NK1) adj1[f] = 0.f;
  __syncthreads();
  if (f < NK0) {
    int best = 0; float bz = -1e30f;
#pragma unroll
    for (int c = 0; c < NK1; c++) {
      float z = lg[f * NK1 + c] + gumbel_at(kk0, kk1, (uint32_t)(f * NK1 + c), (uint32_t)(NK0 * NK1 / 2));
      if (z > bz) { bz = z; best = c; }
    }
    a1s[f] = best; g_a1[f] = best;
  }
  __syncthreads();
  for (int c = 0; c < NK1; c++) {
    float accv = 0.f;
    for (int r = 0; r < NK0; r++) if (a1s[r] == c) accv += g_lat1[r * HH + f];
    float ss = blockReduceSum256(accv * accv, red);
    float nrm = fmaxf(sqrtf(ss), 1e-12f);
    xcn[c][f] = accv / nrm;
  }
  if (f < NK0 * NK0) {
    int r1 = f / NK0, r2 = f % NK0;
    atomicAdd(&adj1[a1s[r1] * NK1 + a1s[r2]], g_adj0[f]);
  }
  __syncthreads();
  float av = (f < NK1 * NK1) ? adj1[f] : 0.f;
  float s = blockReduceSum256(av, red);
  if (f < NK1 * NK1) adj1[f] = av / s;
  __syncthreads();
  for (int c = 0; c < NK1; c++) {
    float m = 0.f;
#pragma unroll
    for (int c2 = 0; c2 < NK1; c2++) m = fmaf(adj1[c * NK1 + c2], xcn[c2][f], m);
    m1[c][f] = m;
  }
  __syncthreads();
  float acc[NK1];
#pragma unroll
  for (int c = 0; c < NK1; c++) acc[c] = 0.f;
  for (int k = 0; k < HH; k++) {
    float w = encW[(size_t)k * HH + f];
#pragma unroll
    for (int c = 0; c < NK1; c++) acc[c] = fmaf(m1[c][k], w, acc[c]);
  }
  float bb = encb[f];
#pragma unroll
  for (int c = 0; c < NK1; c++) g_lat2[c * HH + f] = tanhf(acc[c] + bb);
}

// ---------------- per-cluster fc1 contribution table ----------------
__global__ void __launch_bounds__(256) k_contrib(const float* __restrict__ fc1W) {
  int f = threadIdx.x;
  int c1s[NK0];
#pragma unroll
  for (int c = 0; c < NK0; c++) c1s[c] = g_a1[c];
  float acc[NK0];
#pragma unroll
  for (int c = 0; c < NK0; c++) acc[c] = 0.f;
  for (int k = 0; k < HH; k++) {
    float w1 = fc1W[(size_t)(HH + k) * HH + f];
    float w2 = fc1W[(size_t)(2 * HH + k) * HH + f];
#pragma unroll
    for (int c = 0; c < NK0; c++) {
      acc[c] = fmaf(g_lat1[c * HH + k], w1, acc[c]);
      acc[c] = fmaf(g_lat2[c1s[c] * HH + k], w2, acc[c]);
    }
  }
#pragma unroll
  for (int c = 0; c < NK0; c++) g_contrib[c * HH + f] = acc[c];
}

// ---------------- final fc2 + log_softmax ----------------
__global__ void __launch_bounds__(256) k_final(
    const float* __restrict__ hidden, const float* __restrict__ W,
    const float* __restrict__ bias, float* __restrict__ out)
{
  int warp = threadIdx.x >> 5, lane = threadIdx.x & 31;
  int v = blockIdx.x * 8 + warp;
  int j = lane & 15, h = lane >> 4;
  const float* hr = hidden + (size_t)v * HH;
  float acc = 0.f;
  for (int k = h; k < HH; k += 2) acc = fmaf(hr[k], W[k * NOUTC + j], acc);
  acc += __shfl_xor_sync(0xffffffffu, acc, 16);
  acc += bias[j];
  float mx = acc;
#pragma unroll
  for (int o = 8; o; o >>= 1) mx = fmaxf(mx, __shfl_xor_sync(0xffffffffu, mx, o));
  float e = expf(acc - mx);
  float se = e;
#pragma unroll
  for (int o = 8; o; o >>= 1) se += __shfl_xor_sync(0xffffffffu, se, o);
  if (lane < 16) out[(size_t)v * NOUTC + j] = acc - mx - logf(se);
}

// ---------------- launcher ----------------
extern "C" void kernel_launch(void* const* d_in, const int* in_sizes, int n_in,
                              void* d_out, int out_size) {
  const float* x       = (const float*)d_in[0];
  const int*   ei      = (const int*)  d_in[1];
  const float* ew      = (const float*)d_in[2];
  const float* conv1_W = (const float*)d_in[3];
  const float* conv1_b = (const float*)d_in[4];
  const float* conv2_W = (const float*)d_in[5];
  const float* conv2_b = (const float*)d_in[6];
  const float* ln1_g   = (const float*)d_in[7];
  const float* ln1_b   = (const float*)d_in[8];
  const float* ln2_g   = (const float*)d_in[9];
  const float* ln2_b   = (const float*)d_in[10];
  const float* efc1_W  = (const float*)d_in[11];
  const float* efc1_b  = (const float*)d_in[12];
  const float* efc2_W  = (const float*)d_in[13];
  const float* efc2_b  = (const float*)d_in[14];
  const float* lin0_W  = (const float*)d_in[15];
  const float* lin0_b  = (const float*)d_in[16];
  const float* lin1_W  = (const float*)d_in[17];
  const float* lin1_b  = (const float*)d_in[18];
  const float* enc0_W  = (const float*)d_in[19];
  const float* enc0_b  = (const float*)d_in[20];
  const float* enc1_W  = (const float*)d_in[21];
  const float* enc1_b  = (const float*)d_in[22];
  const float* fc1_W   = (const float*)d_in[23];
  const float* fc1_b   = (const float*)d_in[24];
  const float* fc2_W   = (const float*)d_in[25];
  const float* fc2_b   = (const float*)d_in[26];
  float* out = (float*)d_out;

  float *p_t0, *p_h1, *p_h2, *p_bottom;
  cudaGetSymbolAddress((void**)&p_t0, g_t0);
  cudaGetSymbolAddress((void**)&p_h1, g_h1);
  cudaGetSymbolAddress((void**)&p_h2, g_h2);
  cudaGetSymbolAddress((void**)&p_bottom, g_bottom);

  // folded JAX keys: key(42) = (0,42); fold_in(level) = tf2x32(key, (0, level))
  uint32_t kA0, kA1, kB0, kB1;
  tf2x32(0u, 42u, 0u, 0u, kA0, kA1);
  tf2x32(0u, 42u, 0u, 1u, kB0, kB1);

  dim3 g2(2, 125);

  k_prep<<<63, 256>>>();
  k_hist<<<EE / 256, 256>>>(ei, ew);
  k_scan<<<1, 256>>>();
  k_dinv<<<63, 256>>>();
  k_scatter<<<EE / 256, 256>>>(ei, ew);

  // GCN layer 1
  k_sgemm<<<g2, 256>>>(x, conv1_W, p_t0, FF, FF, HH, HH, 0, 0, nullptr);
  k_spmm_ln_relu<<<NN, 256>>>(p_t0, p_h1, conv1_b, ln1_g, ln1_b);
  // GCN layer 2
  k_sgemm<<<g2, 256>>>(p_h1, conv2_W, p_t0, HH, HH, HH, HH, 0, 0, nullptr);
  k_spmm_ln_relu<<<NN, 256>>>(p_t0, p_h2, conv2_b, ln2_g, ln2_b);

  // bottom = relu([x,h1,h2]@efc1 + b) @ efc2 + b
  k_sgemm<<<g2, 256>>>(x,    efc1_W,                  p_t0, FF, FF, HH, HH, 0, 0, nullptr);
  k_sgemm<<<g2, 256>>>(p_h1, efc1_W + (size_t)FF * HH,        p_t0, HH, HH, HH, HH, 1, 0, nullptr);
  k_sgemm<<<g2, 256>>>(p_h2, efc1_W + (size_t)(FF + HH) * HH, p_t0, HH, HH, HH, HH, 1, 2, efc1_b);
  k_sgemm<<<g2, 256>>>(p_t0, efc2_W, p_bottom, HH, HH, HH, HH, 0, 1, efc2_b);

  // hierarchical pooling
  k_assign0<<<NN / 8, 256>>>(p_bottom, lin0_W, lin0_b, kA0, kA1);
  k_xc0<<<NN / 64, 256>>>();
  k_adj0<<<EE / 4096, 256>>>(ei);
  k_level0<<<1, 256>>>(enc0_W, enc0_b);
  k_level1<<<1, 256>>>(lin1_W, lin1_b, enc1_W, enc1_b, kB0, kB1);
  k_contrib<<<1, 256>>>(fc1_W);

  // hidden = relu(bottom @ fc1[0:256] + fc1_b + contrib[a0]); out = log_softmax(hidden@fc2+b)
  k_sgemm<<<g2, 256>>>(p_bottom, fc1_W, p_t0, HH, HH, HH, HH, 0, 3, fc1_b);
  k_final<<<NN / 8, 256>>>(p_t0, fc2_W, fc2_b, out);
}

// round 3
// speedup vs baseline: 1.3905x; 1.3905x over previous
#include <cuda_runtime.h>
#include <cstdint>
#include <cmath>

#define NN   16000
#define EE   512000
#define FF   200
#define HH   256
#define NK0  10
#define NK1  5
#define NOUTC 16

// ---------------- device scratch (no allocations allowed) ----------------
__device__ float g_t0[NN*HH];
__device__ float g_h1[NN*HH];
__device__ float g_h2[NN*HH];
__device__ float g_bottom[NN*HH];
__device__ int   g_srcs[EE];
__device__ float g_wn[EE];
__device__ int   g_rowptr[NN+1];
__device__ int   g_cnt[NN];
__device__ int   g_fill[NN];
__device__ float g_degw[NN];
__device__ float g_dinv[NN];
__device__ float g_selfn[NN];
__device__ int   g_a0[NN];
__device__ float g_xc0[NK0*HH];
__device__ float g_adj0[NK0*NK0];
__device__ float g_lat1[NK0*HH];
__device__ int   g_a1[NK0];
__device__ float g_lat2[NK1*HH];
__device__ float g_contrib[NK0*HH];

// ---------------- threefry2x32 (exact JAX semantics) ----------------
__host__ __device__ inline void tf2x32(uint32_t k0, uint32_t k1, uint32_t x0, uint32_t x1,
                                       uint32_t& o0, uint32_t& o1) {
  uint32_t ks2 = k0 ^ k1 ^ 0x1BD11BDAu;
#define ROTL32(x,d) (((x)<<(d))|((x)>>(32-(d))))
#define TFRND(r) { x0 += x1; x1 = ROTL32(x1,(r)); x1 ^= x0; }
  x0 += k0; x1 += k1;
  TFRND(13) TFRND(15) TFRND(26) TFRND(6)   x0 += k1;  x1 += ks2 + 1u;
  TFRND(17) TFRND(29) TFRND(16) TFRND(24)  x0 += ks2; x1 += k0 + 2u;
  TFRND(13) TFRND(15) TFRND(26) TFRND(6)   x0 += k0;  x1 += k1 + 3u;
  TFRND(17) TFRND(29) TFRND(16) TFRND(24)  x0 += k1;  x1 += ks2 + 4u;
  TFRND(13) TFRND(15) TFRND(26) TFRND(6)   x0 += ks2; x1 += k0 + 5u;
  o0 = x0; o1 = x1;
#undef TFRND
#undef ROTL32
}

__device__ __forceinline__ float gumbel_at(uint32_t k0, uint32_t k1, uint32_t t, uint32_t half) {
  uint32_t a, b, bits;
  if (t < half) { tf2x32(k0, k1, t, t + half, a, b); bits = a; }
  else          { tf2x32(k0, k1, t - half, t, a, b); bits = b; }
  float u01 = __uint_as_float((bits >> 9) | 0x3f800000u) - 1.0f;
  float u = fmaxf(1e-10f, u01 * (1.0f - 1e-10f) + 1e-10f);
  return -logf(-logf(u));
}

// ---------------- helpers ----------------
__device__ __forceinline__ float blockReduceSum256(float v, float* red) {
#pragma unroll
  for (int o = 16; o; o >>= 1) v += __shfl_xor_sync(0xffffffffu, v, o);
  int w = threadIdx.x >> 5;
  if ((threadIdx.x & 31) == 0) red[w] = v;
  __syncthreads();
  float r;
  if (threadIdx.x < 8) {
    r = red[threadIdx.x];
#pragma unroll
    for (int o = 4; o; o >>= 1) r += __shfl_xor_sync(0xffu, r, o);
    if (threadIdx.x == 0) red[0] = r;
  }
  __syncthreads();
  r = red[0];
  __syncthreads();
  return r;
}

__device__ __forceinline__ uint32_t f2tf(float f) {
  uint32_t r;
  asm("cvt.rna.tf32.f32 %0, %1;" : "=r"(r) : "f"(f));
  return r;
}

__device__ __forceinline__ void mma_tf32(float c[4], const uint32_t a[4], const uint32_t b[2]) {
  asm volatile(
      "mma.sync.aligned.m16n8k8.row.col.f32.tf32.tf32.f32 "
      "{%0,%1,%2,%3}, {%4,%5,%6,%7}, {%8,%9}, {%0,%1,%2,%3};"
      : "+f"(c[0]), "+f"(c[1]), "+f"(c[2]), "+f"(c[3])
      : "r"(a[0]), "r"(a[1]), "r"(a[2]), "r"(a[3]), "r"(b[0]), "r"(b[1]));
}

// ---------------- graph preprocessing ----------------
__global__ void k_prep() {
  int i = blockIdx.x * blockDim.x + threadIdx.x;
  if (i < NN) { g_cnt[i] = 0; g_fill[i] = 0; g_degw[i] = 0.f; }
  if (i < NK0*HH) g_xc0[i] = 0.f;
  if (i < NK0*NK0) g_adj0[i] = 0.f;
}

__global__ void k_hist(const int* __restrict__ ei, const float* __restrict__ ew) {
  int e = blockIdx.x * blockDim.x + threadIdx.x;
  if (e >= EE) return;
  int d = ei[EE + e];
  atomicAdd(&g_cnt[d], 1);
  atomicAdd(&g_degw[d], ew[e]);
}

__global__ void k_scan() {
  __shared__ int totals[256];
  const int CH = 63;
  int t = threadIdx.x;
  int s0 = t * CH;
  int s1 = s0 + CH; if (s1 > NN) s1 = NN;
  int s = 0;
  for (int i = s0; i < s1; i++) s += g_cnt[i];
  totals[t] = s;
  __syncthreads();
  if (t == 0) {
    int run = 0;
    for (int i = 0; i < 256; i++) { int tmp = totals[i]; totals[i] = run; run += tmp; }
  }
  __syncthreads();
  int run = totals[t];
  for (int i = s0; i < s1; i++) { g_rowptr[i] = run; run += g_cnt[i]; }
  if (s0 < NN && s1 == NN) g_rowptr[NN] = run;
}

__global__ void k_dinv() {
  int i = blockIdx.x * blockDim.x + threadIdx.x;
  if (i >= NN) return;
  float deg = g_degw[i] + 1.0f;
  float di = rsqrtf(deg);
  g_dinv[i] = di;
  g_selfn[i] = di * di;
}

__global__ void k_scatter(const int* __restrict__ ei, const float* __restrict__ ew) {
  int e = blockIdx.x * blockDim.x + threadIdx.x;
  if (e >= EE) return;
  int s = ei[e], d = ei[EE + e];
  int pos = g_rowptr[d] + atomicAdd(&g_fill[d], 1);
  g_srcs[pos] = s;
  g_wn[pos] = ew[e] * g_dinv[s] * g_dinv[d];
}

// ---------------- tf32 tensor-core GEMM ----------------
// C[M,N] = sum_seg A_s[M,K_s] @ B[rowoff_s : rowoff_s+K_s, N]
// BM=128, BN=128, BK=16, 256 threads (8 warps as 2x4), warp tile 64x32.
// epi: 0 none, 1 +bias, 2 +bias+relu, 3 +bias+contrib[a0[row]]+relu
__global__ void __launch_bounds__(256) k_tf32gemm(
    const float* __restrict__ A0, const float* __restrict__ A1, const float* __restrict__ A2,
    int K0s, int K1s, int K2s, int lda0, int lda1, int lda2,
    const float* __restrict__ B, int ldb, float* __restrict__ C, int ldc,
    int epi, const float* __restrict__ bias)
{
  __shared__ uint32_t As[16][132];
  __shared__ uint32_t Bs[16][132];
  const int tid = threadIdx.x;
  const int lane = tid & 31, wid = tid >> 5;
  const int warpM = (wid >> 2) * 64, warpN = (wid & 3) * 32;
  const int bm = blockIdx.y * 128, bn = blockIdx.x * 128;

  float c[4][4][4];
#pragma unroll
  for (int mi = 0; mi < 4; mi++)
#pragma unroll
    for (int ni = 0; ni < 4; ni++)
#pragma unroll
      for (int q = 0; q < 4; q++) c[mi][ni][q] = 0.f;

  const float* Aseg[3] = {A0, A1, A2};
  const int    Kseg[3] = {K0s, K1s, K2s};
  const int    Lseg[3] = {lda0, lda1, lda2};
  int rowoff = 0;

  for (int s = 0; s < 3; s++) {
    const int K = Kseg[s];
    if (K == 0) break;
    const float* A = Aseg[s];
    const int lda = Lseg[s];
    const float* Bp = B + (size_t)rowoff * ldb;

    for (int k0 = 0; k0 < K; k0 += 16) {
      const int Krem = K - k0;
      // load A tile (128 rows x 16 k) -> As[k][m], tf32-converted
#pragma unroll
      for (int u = 0; u < 2; u++) {
        int idx = u * 256 + tid;
        int row = idx >> 2, kq = idx & 3;
        int kc = kq * 4;
        uint32_t w0 = 0, w1 = 0, w2 = 0, w3 = 0;
        if (kc < Krem) {
          float4 v = *reinterpret_cast<const float4*>(A + (size_t)(bm + row) * lda + k0 + kc);
          w0 = f2tf(v.x); w1 = f2tf(v.y); w2 = f2tf(v.z); w3 = f2tf(v.w);
        }
        As[kc + 0][row] = w0; As[kc + 1][row] = w1;
        As[kc + 2][row] = w2; As[kc + 3][row] = w3;
      }
      // load B tile (16 k x 128 n) -> Bs[k][n]
#pragma unroll
      for (int u = 0; u < 2; u++) {
        int idx = u * 256 + tid;
        int krow = idx >> 5, col4 = idx & 31;
        uint4 wv = {0u, 0u, 0u, 0u};
        if (krow < Krem) {
          float4 v = *reinterpret_cast<const float4*>(Bp + (size_t)(k0 + krow) * ldb + bn + col4 * 4);
          wv.x = f2tf(v.x); wv.y = f2tf(v.y); wv.z = f2tf(v.z); wv.w = f2tf(v.w);
        }
        *reinterpret_cast<uint4*>(&Bs[krow][col4 * 4]) = wv;
      }
      __syncthreads();

#pragma unroll
      for (int kk = 0; kk < 2; kk++) {
        const int kb = kk * 8;
        const int ks = kb + (lane & 3);
        const int rg = lane >> 2;
        uint32_t af[4][4];
#pragma unroll
        for (int mi = 0; mi < 4; mi++) {
          int row = warpM + mi * 16 + rg;
          af[mi][0] = As[ks][row];
          af[mi][1] = As[ks][row + 8];
          af[mi][2] = As[ks + 4][row];
          af[mi][3] = As[ks + 4][row + 8];
        }
        uint32_t bf[4][2];
#pragma unroll
        for (int ni = 0; ni < 4; ni++) {
          int col = warpN + ni * 8 + rg;
          bf[ni][0] = Bs[ks][col];
          bf[ni][1] = Bs[ks + 4][col];
        }
#pragma unroll
        for (int mi = 0; mi < 4; mi++)
#pragma unroll
          for (int ni = 0; ni < 4; ni++) mma_tf32(c[mi][ni], af[mi], bf[ni]);
      }
      __syncthreads();
    }
    rowoff += K;
  }

  // epilogue
  const int rg = lane >> 2, cg = (lane & 3) * 2;
#pragma unroll
  for (int mi = 0; mi < 4; mi++) {
    int ra = bm + warpM + mi * 16 + rg;
    int rb = ra + 8;
    const float* rtA = (epi == 3) ? (g_contrib + (size_t)g_a0[ra] * HH) : nullptr;
    const float* rtB = (epi == 3) ? (g_contrib + (size_t)g_a0[rb] * HH) : nullptr;
#pragma unroll
    for (int ni = 0; ni < 4; ni++) {
      int cb = bn + warpN + ni * 8 + cg;
      float v0 = c[mi][ni][0], v1 = c[mi][ni][1];
      float v2 = c[mi][ni][2], v3 = c[mi][ni][3];
      if (epi >= 1) { float b0 = bias[cb], b1 = bias[cb + 1]; v0 += b0; v1 += b1; v2 += b0; v3 += b1; }
      if (epi == 3) { v0 += rtA[cb]; v1 += rtA[cb + 1]; v2 += rtB[cb]; v3 += rtB[cb + 1]; }
      if (epi >= 2) { v0 = fmaxf(v0, 0.f); v1 = fmaxf(v1, 0.f); v2 = fmaxf(v2, 0.f); v3 = fmaxf(v3, 0.f); }
      *reinterpret_cast<float2*>(C + (size_t)ra * ldc + cb) = make_float2(v0, v1);
      *reinterpret_cast<float2*>(C + (size_t)rb * ldc + cb) = make_float2(v2, v3);
    }
  }
}

// ---------------- SpMM + self loop + bias + LayerNorm + ReLU ----------------
__global__ void __launch_bounds__(256) k_spmm_ln_relu(
    const float* __restrict__ hin, float* __restrict__ out,
    const float* __restrict__ bias, const float* __restrict__ lng,
    const float* __restrict__ lnb)
{
  int v = blockIdx.x, f = threadIdx.x;
  int p0 = g_rowptr[v], p1 = g_rowptr[v + 1];
  float acc = hin[(size_t)v * HH + f] * g_selfn[v];
  int p = p0;
  for (; p + 4 <= p1; p += 4) {
    int s0 = g_srcs[p], s1 = g_srcs[p + 1], s2 = g_srcs[p + 2], s3 = g_srcs[p + 3];
    float w0 = g_wn[p], w1 = g_wn[p + 1], w2 = g_wn[p + 2], w3 = g_wn[p + 3];
    acc = fmaf(hin[(size_t)s0 * HH + f], w0, acc);
    acc = fmaf(hin[(size_t)s1 * HH + f], w1, acc);
    acc = fmaf(hin[(size_t)s2 * HH + f], w2, acc);
    acc = fmaf(hin[(size_t)s3 * HH + f], w3, acc);
  }
  for (; p < p1; ++p) acc = fmaf(hin[(size_t)g_srcs[p] * HH + f], g_wn[p], acc);
  acc += bias[f];
  __shared__ float red[8];
  float mean = blockReduceSum256(acc, red) * (1.0f / HH);
  float d = acc - mean;
  float var = blockReduceSum256(d * d, red) * (1.0f / HH);
  out[(size_t)v * HH + f] = fmaxf(0.f, d * rsqrtf(var + 1e-5f) * lng[f] + lnb[f]);
}

// ---------------- level-0 assignment ----------------
__global__ void __launch_bounds__(256) k_assign0(
    const float* __restrict__ bottom, const float* __restrict__ W,
    const float* __restrict__ bias, uint32_t kk0, uint32_t kk1)
{
  int warp = threadIdx.x >> 5, lane = threadIdx.x & 31;
  int v = blockIdx.x * 8 + warp;
  float acc[NK0];
#pragma unroll
  for (int c = 0; c < NK0; c++) acc[c] = 0.f;
  const float* br = bottom + (size_t)v * HH;
  for (int k = lane; k < HH; k += 32) {
    float bv = br[k];
#pragma unroll
    for (int c = 0; c < NK0; c++) acc[c] = fmaf(bv, W[k * NK0 + c], acc[c]);
  }
#pragma unroll
  for (int c = 0; c < NK0; c++) {
#pragma unroll
    for (int o = 16; o; o >>= 1) acc[c] += __shfl_xor_sync(0xffffffffu, acc[c], o);
  }
  if (lane == 0) {
    int best = 0; float bz = -1e30f;
#pragma unroll
    for (int c = 0; c < NK0; c++) {
      float z = acc[c] + bias[c] + gumbel_at(kk0, kk1, (uint32_t)(v * NK0 + c), (uint32_t)(NN * NK0 / 2));
      if (z > bz) { bz = z; best = c; }
    }
    g_a0[v] = best;
  }
}

// ---------------- cluster feature sums ----------------
__global__ void __launch_bounds__(256) k_xc0() {
  __shared__ float acc[NK0 * HH];
  int t = threadIdx.x;
#pragma unroll
  for (int r = 0; r < NK0; r++) acc[r * HH + t] = 0.f;
  __syncthreads();
  int v0 = blockIdx.x * 64;
  for (int n = 0; n < 64; n++) {
    int v = v0 + n;
    int c = g_a0[v];
    acc[c * HH + t] += g_bottom[(size_t)v * HH + t];
  }
  __syncthreads();
  for (int r = 0; r < NK0; r++) atomicAdd(&g_xc0[r * HH + t], acc[r * HH + t]);
}

// ---------------- coarse adjacency histogram ----------------
__global__ void __launch_bounds__(256) k_adj0(const int* __restrict__ ei) {
  __shared__ float a[NK0 * NK0];
  int t = threadIdx.x;
  if (t < NK0 * NK0) a[t] = 0.f;
  __syncthreads();
  int base = blockIdx.x * 4096;
  for (int i = t; i < 4096; i += 256) {
    int e = base + i;
    int cs = g_a0[ei[e]], cd = g_a0[ei[EE + e]];
    atomicAdd(&a[cs * NK0 + cd], 1.0f);
  }
  __syncthreads();
  if (t < NK0 * NK0) atomicAdd(&g_adj0[t], a[t]);
}

// ---------------- level-0 coarsening ----------------
__global__ void __launch_bounds__(256) k_level0(const float* __restrict__ encW,
                                                const float* __restrict__ encb) {
  int f = threadIdx.x;
  __shared__ float xcn[NK0][HH];
  __shared__ float adjn[NK0 * NK0];
  __shared__ float msh[NK0][HH];
  __shared__ float red[8];
  for (int r = 0; r < NK0; r++) {
    float x = g_xc0[r * HH + f];
    float ss = blockReduceSum256(x * x, red);
    float nrm = fmaxf(sqrtf(ss), 1e-12f);
    xcn[r][f] = x / nrm;
  }
  float av = (f < NK0 * NK0) ? g_adj0[f] : 0.f;
  float s = blockReduceSum256(av, red);
  if (f < NK0 * NK0) { adjn[f] = av / s; g_adj0[f] = av / s; }
  __syncthreads();
  for (int r = 0; r < NK0; r++) {
    float m = 0.f;
#pragma unroll
    for (int c = 0; c < NK0; c++) m = fmaf(adjn[r * NK0 + c], xcn[c][f], m);
    msh[r][f] = m;
  }
  __syncthreads();
  float acc[NK0];
#pragma unroll
  for (int r = 0; r < NK0; r++) acc[r] = 0.f;
  for (int k = 0; k < HH; k++) {
    float w = encW[(size_t)k * HH + f];
#pragma unroll
    for (int r = 0; r < NK0; r++) acc[r] = fmaf(msh[r][k], w, acc[r]);
  }
  float bb = encb[f];
#pragma unroll
  for (int r = 0; r < NK0; r++) g_lat1[r * HH + f] = tanhf(acc[r] + bb);
}

// ---------------- level-1 ----------------
__global__ void __launch_bounds__(256) k_level1(
    const float* __restrict__ linW, const float* __restrict__ linb,
    const float* __restrict__ encW, const float* __restrict__ encb,
    uint32_t kk0, uint32_t kk1)
{
  int f = threadIdx.x;
  __shared__ float lg[NK0 * NK1];
  __shared__ int a1s[NK0];
  __shared__ float xcn[NK1][HH];
  __shared__ float adj1[NK1 * NK1];
  __shared__ float m1[NK1][HH];
  __shared__ float red[8];
  if (f < NK0 * NK1) {
    int r = f / NK1, c = f % NK1;
    float acc = linb[c];
    for (int k = 0; k < HH; k++) acc = fmaf(g_lat1[r * HH + k], linW[k * NK1 + c], acc);
    lg[f] = acc;
  }
  if (f < NK1 * NK1) adj1[f] = 0.f;
  __syncthreads();
  if (f < NK0) {
    int best = 0; float bz = -1e30f;
#pragma unroll
    for (int c = 0; c < NK1; c++) {
      float z = lg[f * NK1 + c] + gumbel_at(kk0, kk1, (uint32_t)(f * NK1 + c), (uint32_t)(NK0 * NK1 / 2));
      if (z > bz) { bz = z; best = c; }
    }
    a1s[f] = best; g_a1[f] = best;
  }
  __syncthreads();
  for (int c = 0; c < NK1; c++) {
    float accv = 0.f;
    for (int r = 0; r < NK0; r++) if (a1s[r] == c) accv += g_lat1[r * HH + f];
    float ss = blockReduceSum256(accv * accv, red);
    float nrm = fmaxf(sqrtf(ss), 1e-12f);
    xcn[c][f] = accv / nrm;
  }
  if (f < NK0 * NK0) {
    int r1 = f / NK0, r2 = f % NK0;
    atomicAdd(&adj1[a1s[r1] * NK1 + a1s[r2]], g_adj0[f]);
  }
  __syncthreads();
  float av = (f < NK1 * NK1) ? adj1[f] : 0.f;
  float s = blockReduceSum256(av, red);
  if (f < NK1 * NK1) adj1[f] = av / s;
  __syncthreads();
  for (int c = 0; c < NK1; c++) {
    float m = 0.f;
#pragma unroll
    for (int c2 = 0; c2 < NK1; c2++) m = fmaf(adj1[c * NK1 + c2], xcn[c2][f], m);
    m1[c][f] = m;
  }
  __syncthreads();
  float acc[NK1];
#pragma unroll
  for (int c = 0; c < NK1; c++) acc[c] = 0.f;
  for (int k = 0; k < HH; k++) {
    float w = encW[(size_t)k * HH + f];
#pragma unroll
    for (int c = 0; c < NK1; c++) acc[c] = fmaf(m1[c][k], w, acc[c]);
  }
  float bb = encb[f];
#pragma unroll
  for (int c = 0; c < NK1; c++) g_lat2[c * HH + f] = tanhf(acc[c] + bb);
}

// ---------------- per-cluster fc1 contribution table ----------------
__global__ void __launch_bounds__(256) k_contrib(const float* __restrict__ fc1W) {
  int f = threadIdx.x;
  int c1s[NK0];
#pragma unroll
  for (int c = 0; c < NK0; c++) c1s[c] = g_a1[c];
  float acc[NK0];
#pragma unroll
  for (int c = 0; c < NK0; c++) acc[c] = 0.f;
  for (int k = 0; k < HH; k++) {
    float w1 = fc1W[(size_t)(HH + k) * HH + f];
    float w2 = fc1W[(size_t)(2 * HH + k) * HH + f];
#pragma unroll
    for (int c = 0; c < NK0; c++) {
      acc[c] = fmaf(g_lat1[c * HH + k], w1, acc[c]);
      acc[c] = fmaf(g_lat2[c1s[c] * HH + k], w2, acc[c]);
    }
  }
#pragma unroll
  for (int c = 0; c < NK0; c++) g_contrib[c * HH + f] = acc[c];
}

// ---------------- final fc2 + log_softmax ----------------
__global__ void __launch_bounds__(256) k_final(
    const float* __restrict__ hidden, const float* __restrict__ W,
    const float* __restrict__ bias, float* __restrict__ out)
{
  int warp = threadIdx.x >> 5, lane = threadIdx.x & 31;
  int v = blockIdx.x * 8 + warp;
  int j = lane & 15, h = lane >> 4;
  const float* hr = hidden + (size_t)v * HH;
  float acc = 0.f;
  for (int k = h; k < HH; k += 2) acc = fmaf(hr[k], W[k * NOUTC + j], acc);
  acc += __shfl_xor_sync(0xffffffffu, acc, 16);
  acc += bias[j];
  float mx = acc;
#pragma unroll
  for (int o = 8; o; o >>= 1) mx = fmaxf(mx, __shfl_xor_sync(0xffffffffu, mx, o));
  float e = expf(acc - mx);
  float se = e;
#pragma unroll
  for (int o = 8; o; o >>= 1) se += __shfl_xor_sync(0xffffffffu, se, o);
  if (lane < 16) out[(size_t)v * NOUTC + j] = acc - mx - logf(se);
}

// ---------------- launcher ----------------
extern "C" void kernel_launch(void* const* d_in, const int* in_sizes, int n_in,
                              void* d_out, int out_size) {
  const float* x       = (const float*)d_in[0];
  const int*   ei      = (const int*)  d_in[1];
  const float* ew      = (const float*)d_in[2];
  const float* conv1_W = (const float*)d_in[3];
  const float* conv1_b = (const float*)d_in[4];
  const float* conv2_W = (const float*)d_in[5];
  const float* conv2_b = (const float*)d_in[6];
  const float* ln1_g   = (const float*)d_in[7];
  const float* ln1_b   = (const float*)d_in[8];
  const float* ln2_g   = (const float*)d_in[9];
  const float* ln2_b   = (const float*)d_in[10];
  const float* efc1_W  = (const float*)d_in[11];
  const float* efc1_b  = (const float*)d_in[12];
  const float* efc2_W  = (const float*)d_in[13];
  const float* efc2_b  = (const float*)d_in[14];
  const float* lin0_W  = (const float*)d_in[15];
  const float* lin0_b  = (const float*)d_in[16];
  const float* lin1_W  = (const float*)d_in[17];
  const float* lin1_b  = (const float*)d_in[18];
  const float* enc0_W  = (const float*)d_in[19];
  const float* enc0_b  = (const float*)d_in[20];
  const float* enc1_W  = (const float*)d_in[21];
  const float* enc1_b  = (const float*)d_in[22];
  const float* fc1_W   = (const float*)d_in[23];
  const float* fc1_b   = (const float*)d_in[24];
  const float* fc2_W   = (const float*)d_in[25];
  const float* fc2_b   = (const float*)d_in[26];
  float* out = (float*)d_out;

  float *p_t0, *p_h1, *p_h2, *p_bottom;
  cudaGetSymbolAddress((void**)&p_t0, g_t0);
  cudaGetSymbolAddress((void**)&p_h1, g_h1);
  cudaGetSymbolAddress((void**)&p_h2, g_h2);
  cudaGetSymbolAddress((void**)&p_bottom, g_bottom);

  uint32_t kA0, kA1, kB0, kB1;
  tf2x32(0u, 42u, 0u, 0u, kA0, kA1);
  tf2x32(0u, 42u, 0u, 1u, kB0, kB1);

  dim3 g2(2, 125);

  k_prep<<<63, 256>>>();
  k_hist<<<EE / 256, 256>>>(ei, ew);
  k_scan<<<1, 256>>>();
  k_dinv<<<63, 256>>>();
  k_scatter<<<EE / 256, 256>>>(ei, ew);

  // GCN layer 1
  k_tf32gemm<<<g2, 256>>>(x, nullptr, nullptr, FF, 0, 0, FF, 0, 0,
                          conv1_W, HH, p_t0, HH, 0, nullptr);
  k_spmm_ln_relu<<<NN, 256>>>(p_t0, p_h1, conv1_b, ln1_g, ln1_b);
  // GCN layer 2
  k_tf32gemm<<<g2, 256>>>(p_h1, nullptr, nullptr, HH, 0, 0, HH, 0, 0,
                          conv2_W, HH, p_t0, HH, 0, nullptr);
  k_spmm_ln_relu<<<NN, 256>>>(p_t0, p_h2, conv2_b, ln2_g, ln2_b);

  // bottom = relu([x,h1,h2]@efc1 + b) @ efc2 + b   (fused 3-segment GEMM)
  k_tf32gemm<<<g2, 256>>>(x, p_h1, p_h2, FF, HH, HH, FF, HH, HH,
                          efc1_W, HH, p_t0, HH, 2, efc1_b);
  k_tf32gemm<<<g2, 256>>>(p_t0, nullptr, nullptr, HH, 0, 0, HH, 0, 0,
                          efc2_W, HH, p_bottom, HH, 1, efc2_b);

  // hierarchical pooling
  k_assign0<<<NN / 8, 256>>>(p_bottom, lin0_W, lin0_b, kA0, kA1);
  k_xc0<<<NN / 64, 256>>>();
  k_adj0<<<EE / 4096, 256>>>(ei);
  k_level0<<<1, 256>>>(enc0_W, enc0_b);
  k_level1<<<1, 256>>>(lin1_W, lin1_b, enc1_W, enc1_b, kB0, kB1);
  k_contrib<<<1, 256>>>(fc1_W);

  // hidden = relu(bottom @ fc1[0:256] + fc1_b + contrib[a0]); out = log_softmax
  k_tf32gemm<<<g2, 256>>>(p_bottom, nullptr, nullptr, HH, 0, 0, HH, 0, 0,
                          fc1_W, HH, p_t0, HH, 3, fc1_b);
  k_final<<<NN / 8, 256>>>(p_t0, fc2_W, fc2_b, out);
}